// round 7
// baseline (speedup 1.0000x reference)
#include <cuda_runtime.h>
#include <cuda_bf16.h>

#define BATCH     1000000
#define FEAT      128
#define NCLASS    1000
#define NTHREADS  256
#define NBLOCKS   1184                      // 148 SMs * 8 blocks -> one full wave at 32 regs
#define WARPS_PER_BLOCK (NTHREADS / 32)
#define NWARPS    (NBLOCKS * WARPS_PER_BLOCK)   // 9472
#define NTILES    (BATCH / 32)              // 31250 tiles of 32 contiguous rows (exact)

// Per-block partial sums (every block writes its slot every launch -> no zeroing).
__device__ float g_partials[NBLOCKS];
// Ticket counter for last-block-done reduction; reset by the last block each launch.
__device__ int g_count = 0;
// Dynamic tile scheduler. Warp gw's first tile is gw; further tiles come from
// here. Starts at NWARPS; reset by the last block (all grabs are complete by
// then, since every grab precedes that warp's block finishing).
__device__ unsigned g_tile = NWARPS;

__device__ __forceinline__ float warp_sum(float s) {
    #pragma unroll
    for (int o = 16; o; o >>= 1) s += __shfl_xor_sync(0xffffffffu, s, o);
    return s;
}

__global__ __launch_bounds__(NTHREADS, 8) void hinge_fused_kernel(
    const float* __restrict__ x,
    const int* __restrict__ labels,
    const float* __restrict__ centers,
    float* __restrict__ out)
{
    const int lane = threadIdx.x & 31;
    const int wid  = threadIdx.x >> 5;
    const int gw   = blockIdx.x * WARPS_PER_BLOCK + wid;

    const float4* __restrict__ x4 = reinterpret_cast<const float4*>(x);
    const float4* __restrict__ c4 = reinterpret_cast<const float4*>(centers);

    // margin = ||centers[0] - centers[1]|| / 10 (tiny, L1-hit)
    float4 ca = __ldg(&c4[lane]);
    float4 cb = __ldg(&c4[32 + lane]);
    float md0 = ca.x - cb.x, md1 = ca.y - cb.y, md2 = ca.z - cb.z, md3 = ca.w - cb.w;
    const float margin = sqrtf(warp_sum(md0*md0 + md1*md1 + md2*md2 + md3*md3)) * 0.1f;

    float acc = 0.0f;   // 16x-replicated hinge sums; rescaled by 1/16 at the end

    // Dynamic tile loop: first tile is static (gw), next tile is grabbed from
    // the global ticket BEFORE processing the current tile, so the atomic's
    // latency is fully overlapped with 32 rows of work.
    unsigned t = gw;
    while (t < NTILES) {
        unsigned tnext;
        if (lane == 0) tnext = atomicAdd(&g_tile, 1u);
        tnext = __shfl_sync(0xffffffffu, tnext, 0);

        const unsigned tbase = t * 32u;
        const int mylab = __ldcs(&labels[tbase + lane]);   // 32 labels, one coalesced load

        #pragma unroll 2
        for (int k = 0; k < 16; k++) {
            const int lab0 = __shfl_sync(0xffffffffu, mylab, 2 * k);
            const int lab1 = __shfl_sync(0xffffffffu, mylab, 2 * k + 1);

            float4 xv0 = __ldcs(&x4[(tbase + 2u * k) * 32u + lane]);
            float4 xv1 = __ldcs(&x4[(tbase + 2u * k + 1u) * 32u + lane]);
            float4 cv0 = __ldg(&c4[(unsigned)lab0 * 32u + lane]);
            float4 cv1 = __ldg(&c4[(unsigned)lab1 * 32u + lane]);

            float a0 = xv0.x - cv0.x, a1 = xv0.y - cv0.y, a2 = xv0.z - cv0.z, a3 = xv0.w - cv0.w;
            float b0 = xv1.x - cv1.x, b1 = xv1.y - cv1.y, b2 = xv1.z - cv1.z, b3 = xv1.w - cv1.w;
            float s0 = a0*a0 + a1*a1 + a2*a2 + a3*a3;   // row 2k partial
            float s1 = b0*b0 + b1*b1 + b2*b2 + b3*b3;   // row 2k+1 partial

            // Paired reduction: one cross-half exchange puts row0 partials in
            // lanes 0-15 and row1 partials in lanes 16-31, then 4 butterflies
            // within halves. 5 shuffles for 2 rows; result replicated x16.
            const bool hi = (lane & 16) != 0;
            float send = hi ? s0 : s1;
            float recv = __shfl_xor_sync(0xffffffffu, send, 16);
            float z = (hi ? s1 : s0) + recv;
            #pragma unroll
            for (int o = 8; o; o >>= 1) z += __shfl_xor_sync(0xffffffffu, z, o);
            acc += fmaxf(z - margin, 0.0f);
        }

        t = tnext;
    }

    // warp_sum(acc) = 16 * (true warp hinge sum); exact 1/16 rescale.
    const float wacc = warp_sum(acc) * 0.0625f;

    // Block reduce.
    __shared__ float smem[WARPS_PER_BLOCK];
    __shared__ bool is_last;
    if (lane == 0) smem[wid] = wacc;
    __syncthreads();
    if (threadIdx.x == 0) {
        float s = 0.0f;
        #pragma unroll
        for (int i = 0; i < WARPS_PER_BLOCK; i++) s += smem[i];
        g_partials[blockIdx.x] = s;
        __threadfence();
        int ticket = atomicAdd(&g_count, 1);
        is_last = (ticket == NBLOCKS - 1);
    }
    __syncthreads();

    // Last block reduces all partials (f64, fixed order), writes the scalar,
    // and resets the schedulers for the next launch / graph replay.
    if (is_last) {
        __shared__ double sm[NTHREADS];
        double s = 0.0;
        for (int i = threadIdx.x; i < NBLOCKS; i += NTHREADS)
            s += (double)g_partials[i];
        sm[threadIdx.x] = s;
        __syncthreads();
        #pragma unroll
        for (int o = NTHREADS / 2; o; o >>= 1) {
            if (threadIdx.x < o) sm[threadIdx.x] += sm[threadIdx.x + o];
            __syncthreads();
        }
        if (threadIdx.x == 0) {
            out[0] = (float)(sm[0] / (4.0 * (double)BATCH));
            g_count = 0;
            g_tile  = NWARPS;
        }
    }
}

extern "C" void kernel_launch(void* const* d_in, const int* in_sizes, int n_in,
                              void* d_out, int out_size)
{
    const float* x       = (const float*)d_in[0];   // [1e6, 128] f32
    const int*   labels  = (const int*)  d_in[1];   // [1e6] i32
    const float* centers = (const float*)d_in[2];   // [1000, 128] f32
    float*       out     = (float*)d_out;           // scalar f32

    hinge_fused_kernel<<<NBLOCKS, NTHREADS>>>(x, labels, centers, out);
}

// round 8
// speedup vs baseline: 1.1816x; 1.1816x over previous
#include <cuda_runtime.h>
#include <cuda_bf16.h>

#define BATCH     1000000
#define FEAT      128
#define NCLASS    1000
#define NTHREADS  256
#define NBLOCKS   1184                      // 148 SMs * 8 blocks -> one full wave at 32 regs
#define WARPS_PER_BLOCK (NTHREADS / 32)
#define NWARPS    (NBLOCKS * WARPS_PER_BLOCK)   // 9472
#define TILE_ROWS 4
#define NTILES    (BATCH / TILE_ROWS)       // 250000 tiles, 27 rounds, 97.8% utilization

// Per-block partial sums (every block writes its slot every launch -> no zeroing).
__device__ float g_partials[NBLOCKS];
// Ticket counter for last-block-done reduction; reset by the last block each launch.
__device__ int g_count = 0;

__device__ __forceinline__ float warp_sum(float s) {
    #pragma unroll
    for (int o = 16; o; o >>= 1) s += __shfl_xor_sync(0xffffffffu, s, o);
    return s;
}

__global__ __launch_bounds__(NTHREADS, 8) void hinge_fused_kernel(
    const float* __restrict__ x,
    const int* __restrict__ labels,
    const float* __restrict__ centers,
    float* __restrict__ out)
{
    const int lane = threadIdx.x & 31;
    const int wid  = threadIdx.x >> 5;
    const int gw   = blockIdx.x * WARPS_PER_BLOCK + wid;

    const float4* __restrict__ x4 = reinterpret_cast<const float4*>(x);
    const float4* __restrict__ c4 = reinterpret_cast<const float4*>(centers);

    // margin = ||centers[0] - centers[1]|| / 10 (tiny, L1-hit)
    float4 ca = __ldg(&c4[lane]);
    float4 cb = __ldg(&c4[32 + lane]);
    float md0 = ca.x - cb.x, md1 = ca.y - cb.y, md2 = ca.z - cb.z, md3 = ca.w - cb.w;
    const float margin = sqrtf(warp_sum(md0*md0 + md1*md1 + md2*md2 + md3*md3)) * 0.1f;

    float acc = 0.0f;   // 16x-replicated hinge sums; rescaled by 1/16 at the end

    // Static stride-distributed 4-row tiles: 27 rounds, 97.8% warp utilization.
    // One coalesced label sector per tile, labels distributed via shuffles so
    // no label load sits on the center-gather critical path.
    for (unsigned t = gw; t < NTILES; t += NWARPS) {
        const unsigned tbase = t * (unsigned)TILE_ROWS;
        // Lanes 0-3 carry the 4 labels (all lanes load within one 16B sector).
        const int mylab = __ldcs(&labels[tbase + (lane & 3)]);

        #pragma unroll
        for (int k = 0; k < TILE_ROWS / 2; k++) {
            const int lab0 = __shfl_sync(0xffffffffu, mylab, 2 * k);
            const int lab1 = __shfl_sync(0xffffffffu, mylab, 2 * k + 1);

            float4 xv0 = __ldcs(&x4[(tbase + 2u * k) * 32u + lane]);
            float4 xv1 = __ldcs(&x4[(tbase + 2u * k + 1u) * 32u + lane]);
            float4 cv0 = __ldg(&c4[(unsigned)lab0 * 32u + lane]);
            float4 cv1 = __ldg(&c4[(unsigned)lab1 * 32u + lane]);

            float a0 = xv0.x - cv0.x, a1 = xv0.y - cv0.y, a2 = xv0.z - cv0.z, a3 = xv0.w - cv0.w;
            float b0 = xv1.x - cv1.x, b1 = xv1.y - cv1.y, b2 = xv1.z - cv1.z, b3 = xv1.w - cv1.w;
            float s0 = a0*a0 + a1*a1 + a2*a2 + a3*a3;   // row 2k partial
            float s1 = b0*b0 + b1*b1 + b2*b2 + b3*b3;   // row 2k+1 partial

            // Paired reduction: one cross-half exchange puts row0 partials in
            // lanes 0-15 and row1 partials in lanes 16-31, then 4 butterflies
            // within halves. 5 shuffles for 2 rows; result replicated x16.
            const bool hi = (lane & 16) != 0;
            float send = hi ? s0 : s1;
            float recv = __shfl_xor_sync(0xffffffffu, send, 16);
            float z = (hi ? s1 : s0) + recv;
            #pragma unroll
            for (int o = 8; o; o >>= 1) z += __shfl_xor_sync(0xffffffffu, z, o);
            acc += fmaxf(z - margin, 0.0f);
        }
    }

    // warp_sum(acc) = 16 * (true warp hinge sum); exact 1/16 rescale.
    const float wacc = warp_sum(acc) * 0.0625f;

    // Block reduce.
    __shared__ float smem[WARPS_PER_BLOCK];
    __shared__ bool is_last;
    if (lane == 0) smem[wid] = wacc;
    __syncthreads();
    if (threadIdx.x == 0) {
        float s = 0.0f;
        #pragma unroll
        for (int i = 0; i < WARPS_PER_BLOCK; i++) s += smem[i];
        g_partials[blockIdx.x] = s;
        __threadfence();
        int ticket = atomicAdd(&g_count, 1);
        is_last = (ticket == NBLOCKS - 1);
    }
    __syncthreads();

    // Last block reduces all partials (f64, fixed order) and writes the scalar.
    if (is_last) {
        __shared__ double sm[NTHREADS];
        double s = 0.0;
        for (int i = threadIdx.x; i < NBLOCKS; i += NTHREADS)
            s += (double)g_partials[i];
        sm[threadIdx.x] = s;
        __syncthreads();
        #pragma unroll
        for (int o = NTHREADS / 2; o; o >>= 1) {
            if (threadIdx.x < o) sm[threadIdx.x] += sm[threadIdx.x + o];
            __syncthreads();
        }
        if (threadIdx.x == 0) {
            out[0] = (float)(sm[0] / (4.0 * (double)BATCH));
            g_count = 0;   // reset for next launch / graph replay
        }
    }
}

extern "C" void kernel_launch(void* const* d_in, const int* in_sizes, int n_in,
                              void* d_out, int out_size)
{
    const float* x       = (const float*)d_in[0];   // [1e6, 128] f32
    const int*   labels  = (const int*)  d_in[1];   // [1e6] i32
    const float* centers = (const float*)d_in[2];   // [1000, 128] f32
    float*       out     = (float*)d_out;           // scalar f32

    hinge_fused_kernel<<<NBLOCKS, NTHREADS>>>(x, labels, centers, out);
}